// round 16
// baseline (speedup 1.0000x reference)
#include <cuda_runtime.h>
#include <cuda_fp16.h>
#include <cstdint>
#include <math.h>

#define T_SEQ 4096
#define C_DIM 768
#define N_HEAD 12
#define HEAD_D 64
#define NW (C_DIM * C_DIM)
#define SROW 72   // smem row stride in halves (144B: conflict-free ldmatrix + cp.async)

// Q pre-scale: 1/sqrt(64) * log2(e)  (puts S directly in log2 domain)
#define QSC 0.1803368801111204f

// ----------------------------------------------------------------------------
// Device-global scratch (no allocation allowed)
// ----------------------------------------------------------------------------
__device__ __half g_Xh[T_SEQ * C_DIM], g_Xl[T_SEQ * C_DIM];
__device__ __half g_Wh[4 * NW];
__device__ __half g_Qh[N_HEAD * T_SEQ * HEAD_D], g_Ql[N_HEAD * T_SEQ * HEAD_D];
__device__ __half g_Kh[N_HEAD * T_SEQ * HEAD_D];
__device__ __half g_Vh[N_HEAD * T_SEQ * HEAD_D];
__device__ __half g_Oh[T_SEQ * C_DIM];

// ----------------------------------------------------------------------------
// PTX helpers (baseline ISA only — plain sm_103 target)
// ----------------------------------------------------------------------------
__device__ __forceinline__ uint32_t smem_u32(const void* p) {
    uint32_t a;
    asm("{ .reg .u64 t; cvta.to.shared.u64 t, %1; cvt.u32.u64 %0, t; }"
        : "=r"(a) : "l"(p));
    return a;
}

__device__ __forceinline__ void mma_f16(float* c, const uint32_t* a, const uint32_t* b) {
    asm volatile(
        "mma.sync.aligned.m16n8k16.row.col.f32.f16.f16.f32 "
        "{%0,%1,%2,%3}, {%4,%5,%6,%7}, {%8,%9}, {%0,%1,%2,%3};"
        : "+f"(c[0]), "+f"(c[1]), "+f"(c[2]), "+f"(c[3])
        : "r"(a[0]), "r"(a[1]), "r"(a[2]), "r"(a[3]), "r"(b[0]), "r"(b[1]));
}

#define LDSM4(r, a) \
    asm volatile("ldmatrix.sync.aligned.m8n8.x4.shared.b16 {%0,%1,%2,%3}, [%4];" \
        : "=r"((r)[0]), "=r"((r)[1]), "=r"((r)[2]), "=r"((r)[3]) : "r"(a))
#define LDSM4T(r, a) \
    asm volatile("ldmatrix.sync.aligned.m8n8.x4.trans.shared.b16 {%0,%1,%2,%3}, [%4];" \
        : "=r"((r)[0]), "=r"((r)[1]), "=r"((r)[2]), "=r"((r)[3]) : "r"(a))

#define CP16(dst, src) \
    asm volatile("cp.async.cg.shared.global [%0], [%1], 16;" :: "r"(dst), "l"(src))
#define CP_COMMIT() asm volatile("cp.async.commit_group;" ::: "memory")
#define CP_WAIT0() asm volatile("cp.async.wait_group 0;" ::: "memory")
#define CP_WAIT1() asm volatile("cp.async.wait_group 1;" ::: "memory")

__device__ __forceinline__ uint32_t pack_h2(float x, float y) {
    __half2 h = __float22half2_rn(make_float2(x, y));
    return *reinterpret_cast<uint32_t*>(&h);
}

// fp16 hi + residual-lo split of a float pair
__device__ __forceinline__ void split2(float x, float y, uint32_t& hi, uint32_t& lo) {
    __half2 h2 = __float22half2_rn(make_float2(x, y));
    float2 hf = __half22float2(h2);
    __half2 l2 = __float22half2_rn(make_float2(x - hf.x, y - hf.y));
    hi = *reinterpret_cast<uint32_t*>(&h2);
    lo = *reinterpret_cast<uint32_t*>(&l2);
}

// packed 2^x for a float pair -> fp16x2 (elem0 in low half)
__device__ __forceinline__ uint32_t h2exp2(float lo_e, float hi_e) {
    uint32_t d;
    asm("cvt.rn.f16x2.f32 %0, %1, %2;" : "=r"(d) : "f"(hi_e), "f"(lo_e));
    asm("ex2.approx.f16x2 %0, %0;" : "+r"(d));
    return d;
}

// ----------------------------------------------------------------------------
// Pre-convert: x -> fp16 hi/lo ; weights -> fp16 hi only
// ----------------------------------------------------------------------------
#define NX4 (T_SEQ * C_DIM / 4)
#define NW4 (NW / 4)
#define NCONV (NX4 + 4 * NW4)

__global__ __launch_bounds__(256) void convert_kernel(
    const float* __restrict__ x,  const float* __restrict__ wq,
    const float* __restrict__ wk, const float* __restrict__ wv,
    const float* __restrict__ wo)
{
    int i = blockIdx.x * 256 + threadIdx.x;
    if (i >= NCONV) return;
    if (i < NX4) {
        float4 v = ((const float4*)x)[i];
        uint32_t h0, l0, h1, l1;
        split2(v.x, v.y, h0, l0);
        split2(v.z, v.w, h1, l1);
        ((uint2*)g_Xh)[i] = make_uint2(h0, h1);
        ((uint2*)g_Xl)[i] = make_uint2(l0, l1);
    } else {
        int wi = (i - NX4) / NW4;
        size_t off = (i - NX4) % NW4;
        const float* src = (wi == 0) ? wq : (wi == 1) ? wk : (wi == 2) ? wv : wo;
        float4 v = ((const float4*)src)[off];
        ((uint2*)(g_Wh + (size_t)wi * NW))[off] =
            make_uint2(pack_h2(v.x, v.y), pack_h2(v.z, v.w));
    }
}

// ----------------------------------------------------------------------------
// GEMM C[M,N] = A @ W^T.  8 warps (warp: 16 rows), K-chunk 64.
// MODE 0: CTA 128x128, 2-stage (load-before-wait ordering — see R15 postmortem).
//         A=X; z=0 (Q): hi/lo 2-MMA comp; z=1/2: single-MMA.
// MODE 1: CTA 128x64, 3-stage prologue pipeline. A=O fp16, fp32 out.
// Stage layout (halves): A_hi | B | [A_lo]
// ----------------------------------------------------------------------------
template <int MODE>
__global__ __launch_bounds__(256) void gemm_hf(float* __restrict__ outp)
{
    constexpr int BN   = (MODE == 0) ? 128 : 64;
    constexpr int S_B  = 9216;                    // after A_hi (128*72)
    constexpr int S_AL = S_B + BN * SROW;         // MODE 0 only
    constexpr int STG  = (MODE == 0) ? (S_AL + 9216) : S_AL;
    constexpr int NSTG = (MODE == 0) ? 2 : 3;
    constexpr int NT   = BN / 8;                  // c tiles per warp
    constexpr int BP   = BN / 32;                 // B cp.async iterations
    constexpr int NCH  = C_DIM / 64;

    extern __shared__ __half sb[];
    const uint32_t sbase = smem_u32(sb);
    const int tid = threadIdx.x;
    const int w = tid >> 5, lane = tid & 31;
    const int g = lane >> 2, t = lane & 3;
    const int sub = lane >> 3, rrow = lane & 7;
    const int m0 = blockIdx.y * 128, n0 = blockIdx.x * BN;
    const int z = (MODE == 0) ? blockIdx.z : 3;
    const bool comp = (MODE == 0) && (z == 0);   // hi/lo compensation active

    const __half* Ah = (MODE == 0) ? g_Xh : g_Oh;
    const __half* Al = g_Xl;
    const __half* Bh = g_Wh + (size_t)z * NW;

    float c[NT][4];
#pragma unroll
    for (int i = 0; i < NT; i++)
#pragma unroll
        for (int j = 0; j < 4; j++) c[i][j] = 0.0f;

    auto load_stage = [&](int ch) {
        const int k0 = ch * 64;
        const uint32_t se = (ch % NSTG) * STG;
#pragma unroll
        for (int p = 0; p < 4; p++) {
            int slot = tid + p * 256;
            int r = slot >> 3, cc = (slot & 7) * 8;
            CP16(sbase + (se + r * SROW + cc) * 2,
                 &Ah[(size_t)(m0 + r) * C_DIM + k0 + cc]);
            if (comp)
                CP16(sbase + (se + S_AL + r * SROW + cc) * 2,
                     &Al[(size_t)(m0 + r) * C_DIM + k0 + cc]);
        }
#pragma unroll
        for (int p = 0; p < BP; p++) {
            int slot = tid + p * 256;
            int r = slot >> 3, cc = (slot & 7) * 8;
            CP16(sbase + (se + S_B + r * SROW + cc) * 2,
                 &Bh[(size_t)(n0 + r) * C_DIM + k0 + cc]);
        }
        CP_COMMIT();
    };

    auto compute_chunk = [&](int ch) {
        const uint32_t se = (ch % NSTG) * STG;
#pragma unroll
        for (int ks = 0; ks < 4; ks++) {
            uint32_t ah[4], al[4];
            uint32_t aaddr = sbase + (se +
                (16 * w + (sub & 1) * 8 + rrow) * SROW + 16 * ks + (sub >> 1) * 8) * 2;
            LDSM4(ah, aaddr);
            if (comp) LDSM4(al, aaddr + S_AL * 2);
#pragma unroll
            for (int p = 0; p < NT / 2; p++) {
                uint32_t bh[4];
                uint32_t baddr = sbase + (se + S_B +
                    (16 * p + (sub >> 1) * 8 + rrow) * SROW + 16 * ks + (sub & 1) * 8) * 2;
                LDSM4(bh, baddr);
                mma_f16(c[2 * p], ah, bh);
                mma_f16(c[2 * p + 1], ah, bh + 2);
                if (comp) {
                    mma_f16(c[2 * p], al, bh);
                    mma_f16(c[2 * p + 1], al, bh + 2);
                }
            }
        }
    };

    if (NSTG == 2) {
        // 2-stage: issue next load BEFORE the wait so CP_WAIT1 provably
        // drains the older group (R13 ordering; R15's reorder caused NaN).
        load_stage(0);
        for (int ch = 0; ch < NCH; ch++) {
            bool more = (ch + 1 < NCH);
            if (more) load_stage(ch + 1);
            if (more) CP_WAIT1(); else CP_WAIT0();
            __syncthreads();
            compute_chunk(ch);
            __syncthreads();
        }
    } else {
        // 3-stage: 2-deep prologue; load ch+2 after the wait.
        load_stage(0);
        load_stage(1);
        for (int ch = 0; ch < NCH; ch++) {
            if (ch + 1 < NCH) CP_WAIT1(); else CP_WAIT0();
            __syncthreads();
            if (ch + 2 < NCH) load_stage(ch + 2);
            compute_chunk(ch);
        }
    }

    const int r0 = m0 + 16 * w + g;
    if (MODE == 0) {
#pragma unroll
        for (int nt = 0; nt < NT; nt++) {
            const int head = n0 / 64 + (nt >> 3);       // N-tile covers 2 heads
            const int cb = 8 * (nt & 7) + 2 * t;        // column within head
            size_t o1 = ((size_t)head * T_SEQ + r0) * HEAD_D + cb;
            size_t o2 = ((size_t)head * T_SEQ + r0 + 8) * HEAD_D + cb;
            if (z == 0) {
                uint32_t h0, l0, h1, l1;
                split2(c[nt][0] * QSC, c[nt][1] * QSC, h0, l0);
                split2(c[nt][2] * QSC, c[nt][3] * QSC, h1, l1);
                *(uint32_t*)&g_Qh[o1] = h0; *(uint32_t*)&g_Ql[o1] = l0;
                *(uint32_t*)&g_Qh[o2] = h1; *(uint32_t*)&g_Ql[o2] = l1;
            } else {
                __half* dh = (z == 1) ? g_Kh : g_Vh;
                *(uint32_t*)&dh[o1] = pack_h2(c[nt][0], c[nt][1]);
                *(uint32_t*)&dh[o2] = pack_h2(c[nt][2], c[nt][3]);
            }
        }
    } else {
#pragma unroll
        for (int nt = 0; nt < NT; nt++) {
            int cb = n0 + 8 * nt + 2 * t;
            *(float2*)&outp[(size_t)r0 * C_DIM + cb] = make_float2(c[nt][0], c[nt][1]);
            *(float2*)&outp[(size_t)(r0 + 8) * C_DIM + cb] = make_float2(c[nt][2], c[nt][3]);
        }
    }
}

static constexpr int GEMM0_SMEM = 2 * 27648 * 2;  // 110592 B
static constexpr int GEMM1_SMEM = 3 * 13824 * 2;  // 82944 B

// ----------------------------------------------------------------------------
// Flash attention (causal), log2-domain softmax with fp16x2 ex2.
// CTA = (head, 64 q rows), 4 warps; 64-key tiles; 3-stage cp.async pipeline.
// 4 CTAs/SM (reg-tight: ph computed per-ks inside the PV loop).
// S: Q hi/lo x K (2 MMA). P: fp16 direct from ex2. PV: 1 MMA. Row sums: ones-MMA.
// Warp-voted rescale skip when no row max changes.
// ----------------------------------------------------------------------------
#define A_VOFF 4608                      // V offset within stage (64*SROW)
#define A_STG 9216                       // stage elems: 2*64*72
static constexpr int ATTN_SMEM = 3 * A_STG * 2;  // 55296 B

__global__ __launch_bounds__(128, 4) void attn_hf()
{
    extern __shared__ __half sa[];
    const uint32_t sbase = smem_u32(sa);
    const int h = blockIdx.y;
    const int qi = gridDim.x - 1 - blockIdx.x;   // long CTAs first
    const int q0 = qi * 64;
    const int tid = threadIdx.x;
    const int w = tid >> 5, lane = tid & 31;
    const int g = lane >> 2, t = lane & 3;
    const int sub = lane >> 3, rrow = lane & 7;

    const __half* Qhp = g_Qh + (size_t)h * T_SEQ * HEAD_D;
    const __half* Qlp = g_Ql + (size_t)h * T_SEQ * HEAD_D;
    const __half* Khp = g_Kh + (size_t)h * T_SEQ * HEAD_D;
    const __half* Vhp = g_Vh + (size_t)h * T_SEQ * HEAD_D;

    const int r0 = q0 + 16 * w + g;

    uint32_t qh[4][4], ql[4][4];
#pragma unroll
    for (int ks = 0; ks < 4; ks++) {
#pragma unroll
        for (int rr = 0; rr < 2; rr++) {
            size_t base = (size_t)(r0 + 8 * rr) * HEAD_D + 16 * ks + 2 * t;
            qh[ks][rr]     = *(const uint32_t*)&Qhp[base];
            qh[ks][rr + 2] = *(const uint32_t*)&Qhp[base + 8];
            ql[ks][rr]     = *(const uint32_t*)&Qlp[base];
            ql[ks][rr + 2] = *(const uint32_t*)&Qlp[base + 8];
        }
    }

    float o[8][4];
#pragma unroll
    for (int i = 0; i < 8; i++)
#pragma unroll
        for (int j = 0; j < 4; j++) o[i][j] = 0.0f;
    float m_[2] = {-1e30f, -1e30f};
    float lsum[4] = {0.0f, 0.0f, 0.0f, 0.0f};
    const uint32_t ones2[2] = {0x3C003C00u, 0x3C003C00u};

    auto load_stage = [&](int j) {
        const int k0 = j * 64;
        const uint32_t se = (j % 3) * A_STG;
#pragma unroll
        for (int p = 0; p < 4; p++) {
            int slot = tid + p * 128;
            int r = slot >> 3, cc = (slot & 7) * 8;
            size_t go = (size_t)(k0 + r) * HEAD_D + cc;
            uint32_t so = (se + r * SROW + cc) * 2;
            CP16(sbase + so, &Khp[go]);
            CP16(sbase + so + A_VOFF * 2, &Vhp[go]);
        }
        CP_COMMIT();
    };

    const int njt = qi + 1;
    load_stage(0);
    if (njt > 1) load_stage(1);
    for (int j = 0; j < njt; j++) {
        if (j + 1 < njt) CP_WAIT1(); else CP_WAIT0();
        __syncthreads();
        if (j + 2 < njt) load_stage(j + 2);

        const int k0 = j * 64;
        const uint32_t se = (j % 3) * A_STG;
        const bool active = (k0 <= q0 + 16 * w + 15);

        if (active) {
            float s[8][4];
#pragma unroll
            for (int i = 0; i < 8; i++)
#pragma unroll
                for (int e = 0; e < 4; e++) s[i][e] = 0.0f;

            // S (log2 domain) = Q' K^T  (Q hi/lo compensated, K rounded)
#pragma unroll
            for (int ks = 0; ks < 4; ks++) {
#pragma unroll
                for (int p = 0; p < 4; p++) {
                    uint32_t kh[4];
                    uint32_t kaddr = sbase + (se +
                        (16 * p + (sub >> 1) * 8 + rrow) * SROW + 16 * ks + (sub & 1) * 8) * 2;
                    LDSM4(kh, kaddr);
                    mma_f16(s[2 * p], qh[ks], kh);
                    mma_f16(s[2 * p], ql[ks], kh);
                    mma_f16(s[2 * p + 1], qh[ks], kh + 2);
                    mma_f16(s[2 * p + 1], ql[ks], kh + 2);
                }
            }

            // causal mask
            if (k0 + 63 > q0 + 16 * w) {
#pragma unroll
                for (int nt = 0; nt < 8; nt++)
#pragma unroll
                    for (int e = 0; e < 4; e++) {
                        int key = k0 + 8 * nt + 2 * t + (e & 1);
                        int row = r0 + 8 * (e >> 1);
                        if (key > row) s[nt][e] = -1e30f;
                    }
            }

            // running max per row (g, g+8)
            float rmax0 = -1e30f, rmax1 = -1e30f;
#pragma unroll
            for (int nt = 0; nt < 8; nt++) {
                rmax0 = fmaxf(rmax0, fmaxf(s[nt][0], s[nt][1]));
                rmax1 = fmaxf(rmax1, fmaxf(s[nt][2], s[nt][3]));
            }
            rmax0 = fmaxf(rmax0, __shfl_xor_sync(0xffffffffu, rmax0, 1));
            rmax0 = fmaxf(rmax0, __shfl_xor_sync(0xffffffffu, rmax0, 2));
            rmax1 = fmaxf(rmax1, __shfl_xor_sync(0xffffffffu, rmax1, 1));
            rmax1 = fmaxf(rmax1, __shfl_xor_sync(0xffffffffu, rmax1, 2));

            float mn0 = fmaxf(m_[0], rmax0), mn1 = fmaxf(m_[1], rmax1);

            // warp-voted skip: if no row's max moved, corr == 1 exactly
            bool chg = (mn0 > m_[0]) || (mn1 > m_[1]);
            if (__any_sync(0xffffffffu, chg)) {
                float corr0 = exp2f(m_[0] - mn0), corr1 = exp2f(m_[1] - mn1);
                lsum[0] *= corr0; lsum[1] *= corr0;
                lsum[2] *= corr1; lsum[3] *= corr1;
#pragma unroll
                for (int nt = 0; nt < 8; nt++) {
                    o[nt][0] *= corr0;
                    o[nt][1] *= corr0;
                    o[nt][2] *= corr1;
                    o[nt][3] *= corr1;
                }
                m_[0] = mn0; m_[1] = mn1;
            }

            // Per-ks: P fragment from ex2, row-sum ones-MMA, PV MMAs.
            // (keeps only 4 ph regs live; interleaves MUFU with tensor work)
#pragma unroll
            for (int ks = 0; ks < 4; ks++) {
                uint32_t ph[4];
                ph[0] = h2exp2(s[2 * ks][0] - m_[0],     s[2 * ks][1] - m_[0]);
                ph[1] = h2exp2(s[2 * ks][2] - m_[1],     s[2 * ks][3] - m_[1]);
                ph[2] = h2exp2(s[2 * ks + 1][0] - m_[0], s[2 * ks + 1][1] - m_[0]);
                ph[3] = h2exp2(s[2 * ks + 1][2] - m_[1], s[2 * ks + 1][3] - m_[1]);

                mma_f16(lsum, ph, ones2);
#pragma unroll
                for (int p = 0; p < 4; p++) {
                    uint32_t vh[4];
                    uint32_t vaddr = sbase + (se + A_VOFF +
                        (16 * ks + (sub & 1) * 8 + rrow) * SROW + 16 * p + (sub >> 1) * 8) * 2;
                    LDSM4T(vh, vaddr);
                    mma_f16(o[2 * p], ph, vh);
                    mma_f16(o[2 * p + 1], ph, vh + 2);
                }
            }
        }
    }

    // normalize + write O (fp16) in (T, C) layout
    float inv0 = 1.0f / lsum[0], inv1 = 1.0f / lsum[2];
#pragma unroll
    for (int nd = 0; nd < 8; nd++) {
        int col = h * HEAD_D + 8 * nd + 2 * t;
        *(uint32_t*)&g_Oh[(size_t)r0 * C_DIM + col] =
            pack_h2(o[nd][0] * inv0, o[nd][1] * inv0);
        *(uint32_t*)&g_Oh[(size_t)(r0 + 8) * C_DIM + col] =
            pack_h2(o[nd][2] * inv1, o[nd][3] * inv1);
    }
}

// ----------------------------------------------------------------------------
extern "C" void kernel_launch(void* const* d_in, const int* in_sizes, int n_in,
                              void* d_out, int out_size)
{
    const float* x  = (const float*)d_in[0];
    const float* wq = (const float*)d_in[1];
    const float* wk = (const float*)d_in[2];
    const float* wv = (const float*)d_in[3];
    const float* wo = (const float*)d_in[4];
    float* out = (float*)d_out;

    cudaFuncSetAttribute(gemm_hf<0>, cudaFuncAttributeMaxDynamicSharedMemorySize, GEMM0_SMEM);
    cudaFuncSetAttribute(gemm_hf<1>, cudaFuncAttributeMaxDynamicSharedMemorySize, GEMM1_SMEM);
    cudaFuncSetAttribute(attn_hf, cudaFuncAttributeMaxDynamicSharedMemorySize, ATTN_SMEM);

    // 0) one-time conversion
    convert_kernel<<<(NCONV + 255) / 256, 256>>>(x, wq, wk, wv, wo);

    // 1) QKV projections (Q compensated, K/V single-MMA), 128x128 tiles
    gemm_hf<0><<<dim3(C_DIM / 128, T_SEQ / 128, 3), 256, GEMM0_SMEM>>>(nullptr);

    // 2) flash attention: 64-row CTAs, 64-key tiles, 4 CTAs/SM
    attn_hf<<<dim3(T_SEQ / 64, N_HEAD), 128, ATTN_SMEM>>>();

    // 3) output projection -> fp32, 128x64 tiles, 3-stage pipeline
    gemm_hf<1><<<dim3(C_DIM / 64, T_SEQ / 128, 1), 256, GEMM1_SMEM>>>(out);
}

// round 17
// speedup vs baseline: 1.0598x; 1.0598x over previous
#include <cuda_runtime.h>
#include <cuda_fp16.h>
#include <cstdint>
#include <math.h>

#define T_SEQ 4096
#define C_DIM 768
#define N_HEAD 12
#define HEAD_D 64
#define NW (C_DIM * C_DIM)
#define SROW 72   // smem row stride in halves (144B: conflict-free ldmatrix + cp.async)

// Q pre-scale: 1/sqrt(64) * log2(e)  (puts S directly in log2 domain)
#define QSC 0.1803368801111204f

// ----------------------------------------------------------------------------
// Device-global scratch (no allocation allowed)
// ----------------------------------------------------------------------------
__device__ __half g_Xh[T_SEQ * C_DIM], g_Xl[T_SEQ * C_DIM];
__device__ __half g_Wh[4 * NW];
__device__ __half g_Qh[N_HEAD * T_SEQ * HEAD_D], g_Ql[N_HEAD * T_SEQ * HEAD_D];
__device__ __half g_Kh[N_HEAD * T_SEQ * HEAD_D];
__device__ __half g_Vh[N_HEAD * T_SEQ * HEAD_D];
__device__ __half g_Oh[T_SEQ * C_DIM];

// ----------------------------------------------------------------------------
// PTX helpers (baseline ISA only — plain sm_103 target)
// ----------------------------------------------------------------------------
__device__ __forceinline__ uint32_t smem_u32(const void* p) {
    uint32_t a;
    asm("{ .reg .u64 t; cvta.to.shared.u64 t, %1; cvt.u32.u64 %0, t; }"
        : "=r"(a) : "l"(p));
    return a;
}

__device__ __forceinline__ void mma_f16(float* c, const uint32_t* a, const uint32_t* b) {
    asm volatile(
        "mma.sync.aligned.m16n8k16.row.col.f32.f16.f16.f32 "
        "{%0,%1,%2,%3}, {%4,%5,%6,%7}, {%8,%9}, {%0,%1,%2,%3};"
        : "+f"(c[0]), "+f"(c[1]), "+f"(c[2]), "+f"(c[3])
        : "r"(a[0]), "r"(a[1]), "r"(a[2]), "r"(a[3]), "r"(b[0]), "r"(b[1]));
}

#define LDSM4(r, a) \
    asm volatile("ldmatrix.sync.aligned.m8n8.x4.shared.b16 {%0,%1,%2,%3}, [%4];" \
        : "=r"((r)[0]), "=r"((r)[1]), "=r"((r)[2]), "=r"((r)[3]) : "r"(a))
#define LDSM4T(r, a) \
    asm volatile("ldmatrix.sync.aligned.m8n8.x4.trans.shared.b16 {%0,%1,%2,%3}, [%4];" \
        : "=r"((r)[0]), "=r"((r)[1]), "=r"((r)[2]), "=r"((r)[3]) : "r"(a))

#define CP16(dst, src) \
    asm volatile("cp.async.cg.shared.global [%0], [%1], 16;" :: "r"(dst), "l"(src))
#define CP_COMMIT() asm volatile("cp.async.commit_group;" ::: "memory")
#define CP_WAIT0() asm volatile("cp.async.wait_group 0;" ::: "memory")
#define CP_WAIT1() asm volatile("cp.async.wait_group 1;" ::: "memory")
#define CP_WAIT2() asm volatile("cp.async.wait_group 2;" ::: "memory")

__device__ __forceinline__ uint32_t pack_h2(float x, float y) {
    __half2 h = __float22half2_rn(make_float2(x, y));
    return *reinterpret_cast<uint32_t*>(&h);
}

// fp16 hi + residual-lo split of a float pair
__device__ __forceinline__ void split2(float x, float y, uint32_t& hi, uint32_t& lo) {
    __half2 h2 = __float22half2_rn(make_float2(x, y));
    float2 hf = __half22float2(h2);
    __half2 l2 = __float22half2_rn(make_float2(x - hf.x, y - hf.y));
    hi = *reinterpret_cast<uint32_t*>(&h2);
    lo = *reinterpret_cast<uint32_t*>(&l2);
}

// packed 2^x for a float pair -> fp16x2 (elem0 in low half)
__device__ __forceinline__ uint32_t h2exp2(float lo_e, float hi_e) {
    uint32_t d;
    asm("cvt.rn.f16x2.f32 %0, %1, %2;" : "=r"(d) : "f"(hi_e), "f"(lo_e));
    asm("ex2.approx.f16x2 %0, %0;" : "+r"(d));
    return d;
}

// ----------------------------------------------------------------------------
// Pre-convert: x -> fp16 hi/lo ; weights -> fp16 hi only
// ----------------------------------------------------------------------------
#define NX4 (T_SEQ * C_DIM / 4)
#define NW4 (NW / 4)
#define NCONV (NX4 + 4 * NW4)

__global__ __launch_bounds__(256) void convert_kernel(
    const float* __restrict__ x,  const float* __restrict__ wq,
    const float* __restrict__ wk, const float* __restrict__ wv,
    const float* __restrict__ wo)
{
    int i = blockIdx.x * 256 + threadIdx.x;
    if (i >= NCONV) return;
    if (i < NX4) {
        float4 v = ((const float4*)x)[i];
        uint32_t h0, l0, h1, l1;
        split2(v.x, v.y, h0, l0);
        split2(v.z, v.w, h1, l1);
        ((uint2*)g_Xh)[i] = make_uint2(h0, h1);
        ((uint2*)g_Xl)[i] = make_uint2(l0, l1);
    } else {
        int wi = (i - NX4) / NW4;
        size_t off = (i - NX4) % NW4;
        const float* src = (wi == 0) ? wq : (wi == 1) ? wk : (wi == 2) ? wv : wo;
        float4 v = ((const float4*)src)[off];
        ((uint2*)(g_Wh + (size_t)wi * NW))[off] =
            make_uint2(pack_h2(v.x, v.y), pack_h2(v.z, v.w));
    }
}

// ----------------------------------------------------------------------------
// GEMM C[M,N] = A @ W^T.  8 warps (warp: 16 rows), K-chunk 64, 2-stage
// cp.async with load-before-wait ordering (R13-validated; R15 reorder = NaN).
// MODE 0: CTA 128x128. A=X; z=0 (Q): hi/lo 2-MMA comp; z=1/2: single-MMA.
// MODE 1: CTA 128x64 (384 CTAs = wave fit, 4 CTAs/SM). A=O fp16, fp32 out.
// Stage layout (halves): A_hi | B | [A_lo]
// ----------------------------------------------------------------------------
template <int MODE>
__global__ __launch_bounds__(256) void gemm_hf(float* __restrict__ outp)
{
    constexpr int BN   = (MODE == 0) ? 128 : 64;
    constexpr int S_B  = 9216;                    // after A_hi (128*72)
    constexpr int S_AL = S_B + BN * SROW;         // MODE 0 only
    constexpr int STG  = (MODE == 0) ? (S_AL + 9216) : S_AL;
    constexpr int NT   = BN / 8;                  // c tiles per warp
    constexpr int BP   = BN / 32;                 // B cp.async iterations
    constexpr int NCH  = C_DIM / 64;

    extern __shared__ __half sb[];
    const uint32_t sbase = smem_u32(sb);
    const int tid = threadIdx.x;
    const int w = tid >> 5, lane = tid & 31;
    const int g = lane >> 2, t = lane & 3;
    const int sub = lane >> 3, rrow = lane & 7;
    const int m0 = blockIdx.y * 128, n0 = blockIdx.x * BN;
    const int z = (MODE == 0) ? blockIdx.z : 3;
    const bool comp = (MODE == 0) && (z == 0);   // hi/lo compensation active

    const __half* Ah = (MODE == 0) ? g_Xh : g_Oh;
    const __half* Al = g_Xl;
    const __half* Bh = g_Wh + (size_t)z * NW;

    float c[NT][4];
#pragma unroll
    for (int i = 0; i < NT; i++)
#pragma unroll
        for (int j = 0; j < 4; j++) c[i][j] = 0.0f;

    auto load_stage = [&](int ch) {
        const int k0 = ch * 64;
        const uint32_t se = (ch & 1) * STG;
#pragma unroll
        for (int p = 0; p < 4; p++) {
            int slot = tid + p * 256;
            int r = slot >> 3, cc = (slot & 7) * 8;
            CP16(sbase + (se + r * SROW + cc) * 2,
                 &Ah[(size_t)(m0 + r) * C_DIM + k0 + cc]);
            if (comp)
                CP16(sbase + (se + S_AL + r * SROW + cc) * 2,
                     &Al[(size_t)(m0 + r) * C_DIM + k0 + cc]);
        }
#pragma unroll
        for (int p = 0; p < BP; p++) {
            int slot = tid + p * 256;
            int r = slot >> 3, cc = (slot & 7) * 8;
            CP16(sbase + (se + S_B + r * SROW + cc) * 2,
                 &Bh[(size_t)(n0 + r) * C_DIM + k0 + cc]);
        }
        CP_COMMIT();
    };

    load_stage(0);
    for (int ch = 0; ch < NCH; ch++) {
        bool more = (ch + 1 < NCH);
        if (more) load_stage(ch + 1);
        if (more) CP_WAIT1(); else CP_WAIT0();
        __syncthreads();
        const uint32_t se = (ch & 1) * STG;
#pragma unroll
        for (int ks = 0; ks < 4; ks++) {
            uint32_t ah[4], al[4];
            uint32_t aaddr = sbase + (se +
                (16 * w + (sub & 1) * 8 + rrow) * SROW + 16 * ks + (sub >> 1) * 8) * 2;
            LDSM4(ah, aaddr);
            if (comp) LDSM4(al, aaddr + S_AL * 2);
#pragma unroll
            for (int p = 0; p < NT / 2; p++) {
                uint32_t bh[4];
                uint32_t baddr = sbase + (se + S_B +
                    (16 * p + (sub >> 1) * 8 + rrow) * SROW + 16 * ks + (sub & 1) * 8) * 2;
                LDSM4(bh, baddr);
                mma_f16(c[2 * p], ah, bh);
                mma_f16(c[2 * p + 1], ah, bh + 2);
                if (comp) {
                    mma_f16(c[2 * p], al, bh);
                    mma_f16(c[2 * p + 1], al, bh + 2);
                }
            }
        }
        __syncthreads();
    }

    const int r0 = m0 + 16 * w + g;
    if (MODE == 0) {
#pragma unroll
        for (int nt = 0; nt < NT; nt++) {
            const int head = n0 / 64 + (nt >> 3);       // N-tile covers 2 heads
            const int cb = 8 * (nt & 7) + 2 * t;        // column within head
            size_t o1 = ((size_t)head * T_SEQ + r0) * HEAD_D + cb;
            size_t o2 = ((size_t)head * T_SEQ + r0 + 8) * HEAD_D + cb;
            if (z == 0) {
                uint32_t h0, l0, h1, l1;
                split2(c[nt][0] * QSC, c[nt][1] * QSC, h0, l0);
                split2(c[nt][2] * QSC, c[nt][3] * QSC, h1, l1);
                *(uint32_t*)&g_Qh[o1] = h0; *(uint32_t*)&g_Ql[o1] = l0;
                *(uint32_t*)&g_Qh[o2] = h1; *(uint32_t*)&g_Ql[o2] = l1;
            } else {
                __half* dh = (z == 1) ? g_Kh : g_Vh;
                *(uint32_t*)&dh[o1] = pack_h2(c[nt][0], c[nt][1]);
                *(uint32_t*)&dh[o2] = pack_h2(c[nt][2], c[nt][3]);
            }
        }
    } else {
#pragma unroll
        for (int nt = 0; nt < NT; nt++) {
            int cb = n0 + 8 * nt + 2 * t;
            *(float2*)&outp[(size_t)r0 * C_DIM + cb] = make_float2(c[nt][0], c[nt][1]);
            *(float2*)&outp[(size_t)(r0 + 8) * C_DIM + cb] = make_float2(c[nt][2], c[nt][3]);
        }
    }
}

static constexpr int GEMM0_SMEM = 2 * 27648 * 2;  // 110592 B
static constexpr int GEMM1_SMEM = 2 * 13824 * 2;  // 55296 B

// ----------------------------------------------------------------------------
// Flash attention (causal), log2-domain softmax with fp16x2 ex2.
// CTA = (head, 64 q rows), 4 warps; 64-key tiles; 4-stage cp.async pipeline
// (2-deep lookahead hides L2 latency; 3x73.7KB still = 3 CTAs/SM).
// S: Q hi/lo x K (2 MMA). P: fp16 direct from ex2 (per-ks, 4 live regs).
// PV: 1 MMA. Row sums: ones-MMA. Warp-voted rescale skip.
// ----------------------------------------------------------------------------
#define A_VOFF 4608                      // V offset within stage (64*SROW)
#define A_STG 9216                       // stage elems: 2*64*72
static constexpr int ATTN_SMEM = 4 * A_STG * 2;  // 73728 B

__global__ __launch_bounds__(128, 3) void attn_hf()
{
    extern __shared__ __half sa[];
    const uint32_t sbase = smem_u32(sa);
    const int h = blockIdx.y;
    const int qi = gridDim.x - 1 - blockIdx.x;   // long CTAs first
    const int q0 = qi * 64;
    const int tid = threadIdx.x;
    const int w = tid >> 5, lane = tid & 31;
    const int g = lane >> 2, t = lane & 3;
    const int sub = lane >> 3, rrow = lane & 7;

    const __half* Qhp = g_Qh + (size_t)h * T_SEQ * HEAD_D;
    const __half* Qlp = g_Ql + (size_t)h * T_SEQ * HEAD_D;
    const __half* Khp = g_Kh + (size_t)h * T_SEQ * HEAD_D;
    const __half* Vhp = g_Vh + (size_t)h * T_SEQ * HEAD_D;

    const int r0 = q0 + 16 * w + g;

    uint32_t qh[4][4], ql[4][4];
#pragma unroll
    for (int ks = 0; ks < 4; ks++) {
#pragma unroll
        for (int rr = 0; rr < 2; rr++) {
            size_t base = (size_t)(r0 + 8 * rr) * HEAD_D + 16 * ks + 2 * t;
            qh[ks][rr]     = *(const uint32_t*)&Qhp[base];
            qh[ks][rr + 2] = *(const uint32_t*)&Qhp[base + 8];
            ql[ks][rr]     = *(const uint32_t*)&Qlp[base];
            ql[ks][rr + 2] = *(const uint32_t*)&Qlp[base + 8];
        }
    }

    float o[8][4];
#pragma unroll
    for (int i = 0; i < 8; i++)
#pragma unroll
        for (int j = 0; j < 4; j++) o[i][j] = 0.0f;
    float m_[2] = {-1e30f, -1e30f};
    float lsum[4] = {0.0f, 0.0f, 0.0f, 0.0f};
    const uint32_t ones2[2] = {0x3C003C00u, 0x3C003C00u};

    auto load_stage = [&](int j) {
        const int k0 = j * 64;
        const uint32_t se = (j & 3) * A_STG;
#pragma unroll
        for (int p = 0; p < 4; p++) {
            int slot = tid + p * 128;
            int r = slot >> 3, cc = (slot & 7) * 8;
            size_t go = (size_t)(k0 + r) * HEAD_D + cc;
            uint32_t so = (se + r * SROW + cc) * 2;
            CP16(sbase + so, &Khp[go]);
            CP16(sbase + so + A_VOFF * 2, &Vhp[go]);
        }
        CP_COMMIT();
    };

    const int njt = qi + 1;
    load_stage(0);
    if (njt > 1) load_stage(1);
    if (njt > 2) load_stage(2);
    for (int j = 0; j < njt; j++) {
        // drain stage j: newer pending groups = min(njt-1, j+2) - j
        if (j + 2 < njt)      CP_WAIT2();
        else if (j + 1 < njt) CP_WAIT1();
        else                  CP_WAIT0();
        __syncthreads();   // also guards: all warps done with buffer (j+3)&3 == (j-1)&3
        if (j + 3 < njt) load_stage(j + 3);

        const int k0 = j * 64;
        const uint32_t se = (j & 3) * A_STG;
        const bool active = (k0 <= q0 + 16 * w + 15);

        if (active) {
            float s[8][4];
#pragma unroll
            for (int i = 0; i < 8; i++)
#pragma unroll
                for (int e = 0; e < 4; e++) s[i][e] = 0.0f;

            // S (log2 domain) = Q' K^T  (Q hi/lo compensated, K rounded)
#pragma unroll
            for (int ks = 0; ks < 4; ks++) {
#pragma unroll
                for (int p = 0; p < 4; p++) {
                    uint32_t kh[4];
                    uint32_t kaddr = sbase + (se +
                        (16 * p + (sub >> 1) * 8 + rrow) * SROW + 16 * ks + (sub & 1) * 8) * 2;
                    LDSM4(kh, kaddr);
                    mma_f16(s[2 * p], qh[ks], kh);
                    mma_f16(s[2 * p], ql[ks], kh);
                    mma_f16(s[2 * p + 1], qh[ks], kh + 2);
                    mma_f16(s[2 * p + 1], ql[ks], kh + 2);
                }
            }

            // causal mask
            if (k0 + 63 > q0 + 16 * w) {
#pragma unroll
                for (int nt = 0; nt < 8; nt++)
#pragma unroll
                    for (int e = 0; e < 4; e++) {
                        int key = k0 + 8 * nt + 2 * t + (e & 1);
                        int row = r0 + 8 * (e >> 1);
                        if (key > row) s[nt][e] = -1e30f;
                    }
            }

            // running max per row (g, g+8)
            float rmax0 = -1e30f, rmax1 = -1e30f;
#pragma unroll
            for (int nt = 0; nt < 8; nt++) {
                rmax0 = fmaxf(rmax0, fmaxf(s[nt][0], s[nt][1]));
                rmax1 = fmaxf(rmax1, fmaxf(s[nt][2], s[nt][3]));
            }
            rmax0 = fmaxf(rmax0, __shfl_xor_sync(0xffffffffu, rmax0, 1));
            rmax0 = fmaxf(rmax0, __shfl_xor_sync(0xffffffffu, rmax0, 2));
            rmax1 = fmaxf(rmax1, __shfl_xor_sync(0xffffffffu, rmax1, 1));
            rmax1 = fmaxf(rmax1, __shfl_xor_sync(0xffffffffu, rmax1, 2));

            float mn0 = fmaxf(m_[0], rmax0), mn1 = fmaxf(m_[1], rmax1);

            // warp-voted skip: if no row's max moved, corr == 1 exactly
            bool chg = (mn0 > m_[0]) || (mn1 > m_[1]);
            if (__any_sync(0xffffffffu, chg)) {
                float corr0 = exp2f(m_[0] - mn0), corr1 = exp2f(m_[1] - mn1);
                lsum[0] *= corr0; lsum[1] *= corr0;
                lsum[2] *= corr1; lsum[3] *= corr1;
#pragma unroll
                for (int nt = 0; nt < 8; nt++) {
                    o[nt][0] *= corr0;
                    o[nt][1] *= corr0;
                    o[nt][2] *= corr1;
                    o[nt][3] *= corr1;
                }
                m_[0] = mn0; m_[1] = mn1;
            }

            // Per-ks: P fragment from ex2, row-sum ones-MMA, PV MMAs.
            // (4 live ph regs; MUFU interleaved with tensor work)
#pragma unroll
            for (int ks = 0; ks < 4; ks++) {
                uint32_t ph[4];
                ph[0] = h2exp2(s[2 * ks][0] - m_[0],     s[2 * ks][1] - m_[0]);
                ph[1] = h2exp2(s[2 * ks][2] - m_[1],     s[2 * ks][3] - m_[1]);
                ph[2] = h2exp2(s[2 * ks + 1][0] - m_[0], s[2 * ks + 1][1] - m_[0]);
                ph[3] = h2exp2(s[2 * ks + 1][2] - m_[1], s[2 * ks + 1][3] - m_[1]);

                mma_f16(lsum, ph, ones2);
#pragma unroll
                for (int p = 0; p < 4; p++) {
                    uint32_t vh[4];
                    uint32_t vaddr = sbase + (se + A_VOFF +
                        (16 * ks + (sub & 1) * 8 + rrow) * SROW + 16 * p + (sub >> 1) * 8) * 2;
                    LDSM4T(vh, vaddr);
                    mma_f16(o[2 * p], ph, vh);
                    mma_f16(o[2 * p + 1], ph, vh + 2);
                }
            }
        }
    }

    // normalize + write O (fp16) in (T, C) layout
    float inv0 = 1.0f / lsum[0], inv1 = 1.0f / lsum[2];
#pragma unroll
    for (int nd = 0; nd < 8; nd++) {
        int col = h * HEAD_D + 8 * nd + 2 * t;
        *(uint32_t*)&g_Oh[(size_t)r0 * C_DIM + col] =
            pack_h2(o[nd][0] * inv0, o[nd][1] * inv0);
        *(uint32_t*)&g_Oh[(size_t)(r0 + 8) * C_DIM + col] =
            pack_h2(o[nd][2] * inv1, o[nd][3] * inv1);
    }
}

// ----------------------------------------------------------------------------
extern "C" void kernel_launch(void* const* d_in, const int* in_sizes, int n_in,
                              void* d_out, int out_size)
{
    const float* x  = (const float*)d_in[0];
    const float* wq = (const float*)d_in[1];
    const float* wk = (const float*)d_in[2];
    const float* wv = (const float*)d_in[3];
    const float* wo = (const float*)d_in[4];
    float* out = (float*)d_out;

    cudaFuncSetAttribute(gemm_hf<0>, cudaFuncAttributeMaxDynamicSharedMemorySize, GEMM0_SMEM);
    cudaFuncSetAttribute(gemm_hf<1>, cudaFuncAttributeMaxDynamicSharedMemorySize, GEMM1_SMEM);
    cudaFuncSetAttribute(attn_hf, cudaFuncAttributeMaxDynamicSharedMemorySize, ATTN_SMEM);

    // 0) one-time conversion
    convert_kernel<<<(NCONV + 255) / 256, 256>>>(x, wq, wk, wv, wo);

    // 1) QKV projections (Q compensated, K/V single-MMA), 128x128 tiles
    gemm_hf<0><<<dim3(C_DIM / 128, T_SEQ / 128, 3), 256, GEMM0_SMEM>>>(nullptr);

    // 2) flash attention: 64-row CTAs, 64-key tiles, 4-stage pipeline, 3 CTAs/SM
    attn_hf<<<dim3(T_SEQ / 64, N_HEAD), 128, ATTN_SMEM>>>();

    // 3) output projection -> fp32, 128x64 tiles, 2-stage (R13-validated)
    gemm_hf<1><<<dim3(C_DIM / 64, T_SEQ / 128, 1), 256, GEMM1_SMEM>>>(out);
}